// round 5
// baseline (speedup 1.0000x reference)
#include <cuda_runtime.h>
#include <cstdint>

// HistPredictor: splat B*K 2D Gaussians onto 128x128 grids, normalize per batch.
// B=256, K=16, grid 128x128 over [-2,2]^2, MIN_SIGMA=0.001.
//
// R5: 4-CTA cluster per batch (u-quarters). Warp = 32u x 32v tile (lane=u-row),
// per-8-point-quarter ballot skipping with coef-aware threshold, packed f32x2
// incremental exponent + EX2, smem-staged coalesced normalized stores.

#define KMIX 16

__device__ __forceinline__ float ex2f(float x) {
    float r;
    asm("ex2.approx.f32 %0, %1;" : "=f"(r) : "f"(x));
    return r;
}
__device__ __forceinline__ unsigned long long pack2(float lo, float hi) {
    unsigned long long r;
    asm("mov.b64 %0, {%1, %2};" : "=l"(r) : "f"(lo), "f"(hi));
    return r;
}
__device__ __forceinline__ void unpack2(float& lo, float& hi, unsigned long long p) {
    asm("mov.b64 {%0, %1}, %2;" : "=f"(lo), "=f"(hi) : "l"(p));
}
__device__ __forceinline__ unsigned long long add2(unsigned long long a, unsigned long long b) {
    unsigned long long r;
    asm("add.rn.f32x2 %0, %1, %2;" : "=l"(r) : "l"(a), "l"(b));
    return r;
}
__device__ __forceinline__ unsigned long long fma2(unsigned long long a, unsigned long long b,
                                                   unsigned long long c) {
    unsigned long long r;
    asm("fma.rn.f32x2 %0, %1, %2, %3;" : "=l"(r) : "l"(a), "l"(b), "l"(c));
    return r;
}

#define HSTRIDE 132   // padded smem row stride (floats)

__global__ __launch_bounds__(128, 6) __cluster_dims__(4, 1, 1)
void gmm_hist_kernel(const float* __restrict__ mu,
                     const float* __restrict__ sigma,
                     const float* __restrict__ cov12,
                     const float* __restrict__ pi,
                     float* __restrict__ out)
{
    // log2-domain coefficients: e = a2*du^2 + b2*du*dv + c2*dv^2  (<= 0)
    __shared__ float s_a[KMIX], s_b[KMIX], s_c[KMIX], s_c2[KMIX];
    __shared__ float s_mu[KMIX], s_mv[KMIX], s_coef[KMIX], s_lc[KMIX];
    __shared__ float s_R[KMIX], s_S[KMIX], s_R4[KMIX], s_R8[KMIX];
    __shared__ float s_red[4];
    __shared__ float s_part[4];
    __shared__ float s_hist[32 * HSTRIDE];

    const int blk = blockIdx.x;
    const int b = blk >> 2;        // batch
    const int q = blk & 3;         // u-quarter == cluster ctarank
    const int t = threadIdx.x;
    const int w    = t >> 5;       // warp -> v-window
    const int lane = t & 31;       // lane -> u-row

    const float H   = 4.0f / 127.0f;
    const float L2E = 1.4426950408889634f;

    if (t < KMIX) {
        const int idx = b * KMIX + t;
        float su = fmaxf(sigma[idx * 2 + 0], 0.001f);
        float sv = fmaxf(sigma[idx * 2 + 1], 0.001f);
        float su2 = su * su;
        float sv2 = sv * sv;
        float c11 = su2 + 1e-6f;
        float c22 = sv2 + 1e-6f;
        float off = cov12[idx];
        float det_full = c11 * c22 - off * off;
        // valid = (det_full > 0) & ~isnan(det_full); NaN>0 is false -> covered.
        float ia, ib, ic, det;
        if (det_full > 0.0f) {
            float rdet = 1.0f / det_full;
            ia = c22 * rdet;
            ib = -off * rdet;
            ic = c11 * rdet;
            det = det_full;
        } else {
            ia = 1.0f / su2;
            ib = 0.0f;
            ic = 1.0f / sv2;
            det = su2 * sv2;
        }
        float a2 = -0.5f * L2E * ia;
        float b2 = -L2E * ib;
        float c2 = -0.5f * L2E * ic;   // strictly < 0
        s_a[t]  = a2;
        s_b[t]  = b2;
        s_c[t]  = c2;
        s_c2[t] = 2.0f * c2;
        float R = c2 * (H * H);        // quadratic-in-j coefficient, < 0
        s_R[t]  = R;
        s_R4[t] = 4.0f * R;
        s_R8[t] = 8.0f * R;
        s_S[t]  = -0.5f / R;
        s_mu[t] = mu[idx * 2 + 0];
        s_mv[t] = mu[idx * 2 + 1];
        float coef = pi[idx] / (6.283185307179586f * sqrtf(det + 1e-6f));
        s_coef[t] = coef;
        s_lc[t]   = __log2f(coef);     // -inf for coef==0 -> always skipped
    }
    __syncthreads();

    // coef-aware threshold base: skip where e + lc_k < lc_max - 20
    float lcmax = s_lc[0];
#pragma unroll
    for (int k = 1; k < KMIX; k++) lcmax = fmaxf(lcmax, s_lc[k]);
    const float thr_base = lcmax - 20.0f;

    // lane -> u-row of this quarter; warp -> 32-wide v window
    const int u  = q * 32 + lane;
    const int v0 = w * 32;
    const float uc    = -2.0f + (float)u  * H;
    const float vbase = -2.0f + (float)v0 * H;

    unsigned long long acc[16];      // packed pairs (j even, j odd)
#pragma unroll
    for (int i = 0; i < 16; i++) acc[i] = 0ull;

#pragma unroll 1
    for (int k = 0; k < KMIX; k++) {
        const float du  = uc    - s_mu[k];
        const float dv0 = vbase - s_mv[k];
        // e(j) = P + Q*j + R*j^2,  dv = dv0 + j*H
        const float R = s_R[k];
        const float Q = fmaf(s_c2[k], dv0, s_b[k] * du) * H;
        const float P = fmaf(fmaf(s_b[k], dv0, s_a[k] * du), du, (s_c[k] * dv0) * dv0);
        const float thr = thr_base - s_lc[k];

        // boundary values at j = 0, 8, 16, 24, 32 (concave parabola)
        float e0  = P;
        float e8  = fmaf(8.0f,  fmaf(R, 8.0f,  Q), P);
        float e16 = fmaf(16.0f, fmaf(R, 16.0f, Q), P);
        float e24 = fmaf(24.0f, fmaf(R, 24.0f, Q), P);
        float e32 = fmaf(32.0f, fmaf(R, 32.0f, Q), P);
        // vertex
        float jc = fminf(fmaxf(Q * s_S[k], 0.0f), 31.0f);
        float ev = fmaf(jc, fmaf(R, jc, Q), P);

        float b0 = fmaxf(e0,  e8);
        float b1 = fmaxf(e8,  e16);
        float b2q = fmaxf(e16, e24);
        float b3 = fmaxf(e24, e32);
        b0  = (fabsf(jc -  4.0f) < 4.5f) ? fmaxf(b0,  ev) : b0;
        b1  = (fabsf(jc - 12.0f) < 4.5f) ? fmaxf(b1,  ev) : b1;
        b2q = (fabsf(jc - 20.0f) < 4.5f) ? fmaxf(b2q, ev) : b2q;
        b3  = (fabsf(jc - 28.0f) < 4.5f) ? fmaxf(b3,  ev) : b3;

        unsigned live = 0;
        if (__ballot_sync(0xffffffffu, b0  >= thr)) live |= 1u;
        if (__ballot_sync(0xffffffffu, b1  >= thr)) live |= 2u;
        if (__ballot_sync(0xffffffffu, b2q >= thr)) live |= 4u;
        if (__ballot_sync(0xffffffffu, b3  >= thr)) live |= 8u;
        if (live == 0u) continue;

        const float coef = s_coef[k];
        const unsigned long long coefp = pack2(coef, coef);
        const unsigned long long stp   = pack2(s_R8[k], s_R8[k]);
        const float twoQ = Q + Q;
        const float R4   = s_R4[k];
        const float ebnd[4] = {e0, e8, e16, e24};

#pragma unroll
        for (int qi = 0; qi < 4; qi++) {
            if (!(live & (1u << qi))) continue;
            const float j0f = (float)(8 * qi);
            const float ej0 = ebnd[qi];
            const float ej1 = ej0 + fmaf(R, 2.0f * j0f + 1.0f, Q);
            float d0 = fmaf(R, 4.0f * j0f + 4.0f, twoQ);
            unsigned long long ep = pack2(ej0, ej1);
            unsigned long long dp = pack2(d0, d0 + R4);
#pragma unroll
            for (int i = 0; i < 4; i++) {
                float elo, ehi;
                unpack2(elo, ehi, ep);
                unsigned long long gp = pack2(ex2f(elo), ex2f(ehi));
                acc[4 * qi + i] = fma2(coefp, gp, acc[4 * qi + i]);
                ep = add2(ep, dp);
                dp = add2(dp, stp);
            }
        }
    }

    // stage tile into smem: lane = u-row, cols [v0, v0+32)
    {
        float* hp = s_hist + lane * HSTRIDE + v0;
#pragma unroll
        for (int i = 0; i < 16; i += 2) {
            float x0, x1, x2, x3;
            unpack2(x0, x1, acc[i]);
            unpack2(x2, x3, acc[i + 1]);
            *reinterpret_cast<float4*>(hp + i * 2) = make_float4(x0, x1, x2, x3);
        }
    }

    // CTA partial sum (this u-quarter)
    float s = 0.0f;
#pragma unroll
    for (int i = 0; i < 16; i++) {
        float lo, hi;
        unpack2(lo, hi, acc[i]);
        s += lo + hi;
    }
#pragma unroll
    for (int o = 16; o > 0; o >>= 1) s += __shfl_xor_sync(0xffffffffu, s, o);
    if (lane == 0) s_red[w] = s;
    __syncthreads();

    // Thread 0 scatters this CTA's partial into slot q of all 4 cluster CTAs.
    if (t == 0) {
        float mysum = s_red[0] + s_red[1] + s_red[2] + s_red[3];
        uint32_t laddr;
        asm("{ .reg .u64 tmp; cvta.to.shared.u64 tmp, %1; cvt.u32.u64 %0, tmp; }"
            : "=r"(laddr) : "l"(&s_part[q]));
#pragma unroll
        for (int r = 0; r < 4; r++) {
            uint32_t raddr;
            asm("mapa.shared::cluster.u32 %0, %1, %2;" : "=r"(raddr) : "r"(laddr), "r"(r));
            asm volatile("st.shared::cluster.f32 [%0], %1;" :: "r"(raddr), "f"(mysum)
                         : "memory");
        }
    }
    // Cluster barrier: orders DSMEM stores, makes all 4 partials visible;
    // also a full-CTA barrier ordering s_hist for the read below.
    asm volatile("barrier.cluster.arrive.aligned;" ::: "memory");
    asm volatile("barrier.cluster.wait.aligned;"   ::: "memory");

    const float tot = (s_part[0] + s_part[1]) + (s_part[2] + s_part[3]);
    const float inv = (tot > 0.0f) ? (1.0f / tot) : 1.0f;

    // coalesced normalized store: thread t -> row (t>>2), v-chunk (t&3)*32
    {
        const int r  = t >> 2;
        const int vc = (t & 3) * 32;
        const float* hp = s_hist + r * HSTRIDE + vc;
        float* op = out + (size_t)b * 16384 + (size_t)(q * 32 + r) * 128 + vc;
#pragma unroll
        for (int p = 0; p < 8; p++) {
            float4 x = *reinterpret_cast<const float4*>(hp + 4 * p);
            x.x *= inv; x.y *= inv; x.z *= inv; x.w *= inv;
            *reinterpret_cast<float4*>(op + 4 * p) = x;
        }
    }
}

extern "C" void kernel_launch(void* const* d_in, const int* in_sizes, int n_in,
                              void* d_out, int out_size)
{
    const float* mu    = (const float*)d_in[0];
    const float* sigma = (const float*)d_in[1];
    const float* cov12 = (const float*)d_in[2];
    const float* pi    = (const float*)d_in[3];
    float* out = (float*)d_out;
    gmm_hist_kernel<<<1024, 128>>>(mu, sigma, cov12, pi, out);
}

// round 6
// speedup vs baseline: 1.2627x; 1.2627x over previous
#include <cuda_runtime.h>
#include <cstdint>

// HistPredictor: splat B*K 2D Gaussians onto 128x128 grids, normalize per batch.
// B=256, K=16, grid 128x128 over [-2,2]^2, MIN_SIGMA=0.001.
//
// R6: R4 structure (4-CTA cluster per batch, DSMEM norm exchange) with a
// dependency-free inner loop: e(j) = P' + Q*j + R*j^2 evaluated directly via
// immediate-multiplier FFMAs (log2 domain, log2(coef) folded into P'), one EX2
// per point, FADD accumulate. Coef-aware warp-uniform skip, 1 ballot per k.

#define KMIX 16

__device__ __forceinline__ float ex2f(float x) {
    float r;
    asm("ex2.approx.f32 %0, %1;" : "=f"(r) : "f"(x));
    return r;
}

__global__ __launch_bounds__(128, 8) __cluster_dims__(4, 1, 1)
void gmm_hist_kernel(const float* __restrict__ mu,
                     const float* __restrict__ sigma,
                     const float* __restrict__ cov12,
                     const float* __restrict__ pi,
                     float* __restrict__ out)
{
    // log2-domain coefficients: e = a2*du^2 + b2*du*dv + c2*dv^2 + lc  (<= lc)
    __shared__ float s_a[KMIX], s_b[KMIX], s_c[KMIX], s_c2[KMIX];
    __shared__ float s_mu[KMIX], s_mv[KMIX], s_lc[KMIX];
    __shared__ float s_R[KMIX], s_S[KMIX];
    __shared__ float s_red[4];
    __shared__ float s_part[4];

    const int blk = blockIdx.x;
    const int b = blk >> 2;        // batch
    const int q = blk & 3;         // u-quarter == cluster ctarank
    const int t = threadIdx.x;

    const float H   = 4.0f / 127.0f;
    const float L2E = 1.4426950408889634f;

    if (t < KMIX) {
        const int idx = b * KMIX + t;
        float su = fmaxf(sigma[idx * 2 + 0], 0.001f);
        float sv = fmaxf(sigma[idx * 2 + 1], 0.001f);
        float su2 = su * su;
        float sv2 = sv * sv;
        float c11 = su2 + 1e-6f;
        float c22 = sv2 + 1e-6f;
        float off = cov12[idx];
        float det_full = c11 * c22 - off * off;
        // valid = (det_full > 0) & ~isnan(det_full); NaN>0 is false -> covered.
        float ia, ib, ic, det;
        if (det_full > 0.0f) {
            float rdet = 1.0f / det_full;
            ia = c22 * rdet;
            ib = -off * rdet;
            ic = c11 * rdet;
            det = det_full;
        } else {
            ia = 1.0f / su2;
            ib = 0.0f;
            ic = 1.0f / sv2;
            det = su2 * sv2;
        }
        float a2 = -0.5f * L2E * ia;
        float b2 = -L2E * ib;
        float c2 = -0.5f * L2E * ic;   // strictly < 0
        s_a[t]  = a2;
        s_b[t]  = b2;
        s_c[t]  = c2;
        s_c2[t] = 2.0f * c2;
        float R = c2 * (H * H);        // quadratic-in-j coefficient, < 0
        s_R[t]  = R;
        s_S[t]  = -0.5f / R;
        s_mu[t] = mu[idx * 2 + 0];
        s_mv[t] = mu[idx * 2 + 1];
        float coef = pi[idx] / (6.283185307179586f * sqrtf(det + 1e-6f));
        s_lc[t]   = __log2f(coef);     // -inf for coef==0
    }
    __syncthreads();

    // coef-aware skip threshold: keep mixture wherever 2^(e+lc) > 2^(lcmax-22)
    float lcmax = s_lc[0];
#pragma unroll
    for (int k = 1; k < KMIX; k++) lcmax = fmaxf(lcmax, s_lc[k]);
    const float thr = lcmax - 22.0f;

    // Thread t owns u = q*32 + (t>>2), v in [(t&3)*32, +32)
    const int u  = q * 32 + (t >> 2);
    const int v0 = (t & 3) * 32;
    const float uc    = -2.0f + (float)u  * H;
    const float vbase = -2.0f + (float)v0 * H;

    float acc[32];
#pragma unroll
    for (int j = 0; j < 32; j++) acc[j] = 0.0f;

#pragma unroll 1
    for (int k = 0; k < KMIX; k++) {
        const float du  = uc    - s_mu[k];
        const float dv0 = vbase - s_mv[k];
        // e(j) = P' + Q*j + R*j^2,  dv = dv0 + j*H,  P' includes log2(coef)
        const float R = s_R[k];
        const float Q = fmaf(s_c2[k], dv0, s_b[k] * du) * H;
        const float P = fmaf(fmaf(s_b[k], dv0, s_a[k] * du), du,
                             fmaf(s_c[k] * dv0, dv0, s_lc[k]));

        // warp-uniform skip: max of concave e over j in [0,31] vs threshold
        float jc = fminf(fmaxf(Q * s_S[k], 0.0f), 31.0f);
        float ev = fmaf(jc, fmaf(R, jc, Q), P);
        if (__ballot_sync(0xffffffffu, ev >= thr) == 0u) continue;

        // dependency-free direct evaluation: j and j as immediates
#pragma unroll
        for (int j = 0; j < 32; j++) {
            const float jf = (float)j;
            float e = fmaf(jf, fmaf(R, jf, Q), P);   // 2 x FFMA (imm multiplier)
            acc[j] += ex2f(e);                       // MUFU.EX2 + FADD
        }
    }

    // CTA partial sum (this u-quarter)
    float s = 0.0f;
#pragma unroll
    for (int j = 0; j < 32; j++) s += acc[j];
#pragma unroll
    for (int o = 16; o > 0; o >>= 1) s += __shfl_xor_sync(0xffffffffu, s, o);
    const int warp = t >> 5;
    const int lane = t & 31;
    if (lane == 0) s_red[warp] = s;
    __syncthreads();

    // Thread 0 scatters this CTA's partial into slot q of all 4 cluster CTAs.
    if (t == 0) {
        float mysum = s_red[0] + s_red[1] + s_red[2] + s_red[3];
        uint32_t laddr;
        asm("{ .reg .u64 tmp; cvta.to.shared.u64 tmp, %1; cvt.u32.u64 %0, tmp; }"
            : "=r"(laddr) : "l"(&s_part[q]));
#pragma unroll
        for (int r = 0; r < 4; r++) {
            uint32_t raddr;
            asm("mapa.shared::cluster.u32 %0, %1, %2;" : "=r"(raddr) : "r"(laddr), "r"(r));
            asm volatile("st.shared::cluster.f32 [%0], %1;" :: "r"(raddr), "f"(mysum)
                         : "memory");
        }
    }
    // Cluster barrier: arrive(release) orders the DSMEM stores; wait(acquire)
    // makes all 4 partials visible in local s_part.
    asm volatile("barrier.cluster.arrive.aligned;" ::: "memory");
    asm volatile("barrier.cluster.wait.aligned;"   ::: "memory");

    const float tot = (s_part[0] + s_part[1]) + (s_part[2] + s_part[3]);
    const float inv = (tot > 0.0f) ? (1.0f / tot) : 1.0f;

    // normalized store (coalesced float4)
    float* op = out + (size_t)b * 16384 + (size_t)u * 128 + v0;
#pragma unroll
    for (int j = 0; j < 32; j += 4) {
        float4 w = make_float4(acc[j] * inv, acc[j + 1] * inv,
                               acc[j + 2] * inv, acc[j + 3] * inv);
        *reinterpret_cast<float4*>(op + j) = w;
    }
}

extern "C" void kernel_launch(void* const* d_in, const int* in_sizes, int n_in,
                              void* d_out, int out_size)
{
    const float* mu    = (const float*)d_in[0];
    const float* sigma = (const float*)d_in[1];
    const float* cov12 = (const float*)d_in[2];
    const float* pi    = (const float*)d_in[3];
    float* out = (float*)d_out;
    gmm_hist_kernel<<<1024, 128>>>(mu, sigma, cov12, pi, out);
}

// round 7
// speedup vs baseline: 1.3846x; 1.0965x over previous
#include <cuda_runtime.h>
#include <cstdint>

// HistPredictor: splat B*K 2D Gaussians onto 128x128 grids, normalize per batch.
// B=256, K=16, grid 128x128 over [-2,2]^2, MIN_SIGMA=0.001.
//
// R7: R6 structure (4-CTA cluster per batch, DSMEM norm exchange, FFMA-imm
// exponent eval, coef-aware skip) with EX2 done as ex2.approx.f16x2:
// exponents rebased by -lcmax (<=0, f16-safe; 2^lcmax cancels in normalize),
// packed 2-at-a-time -> one MUFU op per 2 points, fp32 accumulation.

#define KMIX 16

__global__ __launch_bounds__(128, 8) __cluster_dims__(4, 1, 1)
void gmm_hist_kernel(const float* __restrict__ mu,
                     const float* __restrict__ sigma,
                     const float* __restrict__ cov12,
                     const float* __restrict__ pi,
                     float* __restrict__ out)
{
    // log2-domain coefficients: e = a2*du^2 + b2*du*dv + c2*dv^2 + (lc - lcmax)
    __shared__ float s_a[KMIX], s_b[KMIX], s_c[KMIX], s_c2[KMIX];
    __shared__ float s_mu[KMIX], s_mv[KMIX], s_lc[KMIX];
    __shared__ float s_R[KMIX], s_S[KMIX];
    __shared__ float s_red[4];
    __shared__ float s_part[4];

    const int blk = blockIdx.x;
    const int b = blk >> 2;        // batch
    const int q = blk & 3;         // u-quarter == cluster ctarank
    const int t = threadIdx.x;

    const float H   = 4.0f / 127.0f;
    const float L2E = 1.4426950408889634f;

    if (t < KMIX) {
        const int idx = b * KMIX + t;
        float su = fmaxf(sigma[idx * 2 + 0], 0.001f);
        float sv = fmaxf(sigma[idx * 2 + 1], 0.001f);
        float su2 = su * su;
        float sv2 = sv * sv;
        float c11 = su2 + 1e-6f;
        float c22 = sv2 + 1e-6f;
        float off = cov12[idx];
        float det_full = c11 * c22 - off * off;
        // valid = (det_full > 0) & ~isnan(det_full); NaN>0 is false -> covered.
        float ia, ib, ic, det;
        if (det_full > 0.0f) {
            float rdet = 1.0f / det_full;
            ia = c22 * rdet;
            ib = -off * rdet;
            ic = c11 * rdet;
            det = det_full;
        } else {
            ia = 1.0f / su2;
            ib = 0.0f;
            ic = 1.0f / sv2;
            det = su2 * sv2;
        }
        float a2 = -0.5f * L2E * ia;
        float b2 = -L2E * ib;
        float c2 = -0.5f * L2E * ic;   // strictly < 0
        s_a[t]  = a2;
        s_b[t]  = b2;
        s_c[t]  = c2;
        s_c2[t] = 2.0f * c2;
        float R = c2 * (H * H);        // quadratic-in-j coefficient, < 0
        s_R[t]  = R;
        s_S[t]  = -0.5f / R;
        s_mu[t] = mu[idx * 2 + 0];
        s_mv[t] = mu[idx * 2 + 1];
        float coef = pi[idx] / (6.283185307179586f * sqrtf(det + 1e-6f));
        s_lc[t]   = __log2f(coef);     // -inf for coef==0
    }
    __syncthreads();

    // rebase: all exponents shifted by -lcmax so e' <= 0 (f16-safe).
    // 2^lcmax cancels in the final normalization (same lcmax across cluster).
    float lcmax = s_lc[0];
#pragma unroll
    for (int k = 1; k < KMIX; k++) lcmax = fmaxf(lcmax, s_lc[k]);

    // Thread t owns u = q*32 + (t>>2), v in [(t&3)*32, +32)
    const int u  = q * 32 + (t >> 2);
    const int v0 = (t & 3) * 32;
    const float uc    = -2.0f + (float)u  * H;
    const float vbase = -2.0f + (float)v0 * H;

    float acc[32];
#pragma unroll
    for (int j = 0; j < 32; j++) acc[j] = 0.0f;

#pragma unroll 1
    for (int k = 0; k < KMIX; k++) {
        const float du  = uc    - s_mu[k];
        const float dv0 = vbase - s_mv[k];
        // e(j) = P' + Q*j + R*j^2,  dv = dv0 + j*H,  P' includes lc - lcmax
        const float R = s_R[k];
        const float Q = fmaf(s_c2[k], dv0, s_b[k] * du) * H;
        const float P = fmaf(fmaf(s_b[k], dv0, s_a[k] * du), du,
                             fmaf(s_c[k] * dv0, dv0, s_lc[k] - lcmax));

        // warp-uniform skip: max of concave e' over j in [0,31] vs -22
        float jc = fminf(fmaxf(Q * s_S[k], 0.0f), 31.0f);
        float ev = fmaf(jc, fmaf(R, jc, Q), P);
        if (__ballot_sync(0xffffffffu, ev >= -22.0f) == 0u) continue;

        // dependency-free pairs: fp32 exponents, one f16x2 EX2 per 2 points
#pragma unroll
        for (int j = 0; j < 32; j += 2) {
            const float j0 = (float)j;
            const float j1 = (float)(j + 1);
            float e0 = fmaf(j0, fmaf(R, j0, Q), P);   // FFMA-imm x2
            float e1 = fmaf(j1, fmaf(R, j1, Q), P);
            uint32_t g2;
            asm("{\n\t"
                ".reg .b32 h2;\n\t"
                "cvt.rn.f16x2.f32 h2, %1, %2;\n\t"    // hi = e1, lo = e0
                "ex2.approx.f16x2 %0, h2;\n\t"
                "}"
                : "=r"(g2) : "f"(e1), "f"(e0));
            float g0, g1;
            asm("{\n\t"
                ".reg .b16 lo, hi;\n\t"
                "mov.b32 {lo, hi}, %2;\n\t"
                "cvt.f32.f16 %0, lo;\n\t"
                "cvt.f32.f16 %1, hi;\n\t"
                "}"
                : "=f"(g0), "=f"(g1) : "r"(g2));
            acc[j]     += g0;
            acc[j + 1] += g1;
        }
    }

    // CTA partial sum (this u-quarter, rebased domain)
    float s = 0.0f;
#pragma unroll
    for (int j = 0; j < 32; j++) s += acc[j];
#pragma unroll
    for (int o = 16; o > 0; o >>= 1) s += __shfl_xor_sync(0xffffffffu, s, o);
    const int warp = t >> 5;
    const int lane = t & 31;
    if (lane == 0) s_red[warp] = s;
    __syncthreads();

    // Thread 0 scatters this CTA's partial into slot q of all 4 cluster CTAs.
    if (t == 0) {
        float mysum = s_red[0] + s_red[1] + s_red[2] + s_red[3];
        uint32_t laddr;
        asm("{ .reg .u64 tmp; cvta.to.shared.u64 tmp, %1; cvt.u32.u64 %0, tmp; }"
            : "=r"(laddr) : "l"(&s_part[q]));
#pragma unroll
        for (int r = 0; r < 4; r++) {
            uint32_t raddr;
            asm("mapa.shared::cluster.u32 %0, %1, %2;" : "=r"(raddr) : "r"(laddr), "r"(r));
            asm volatile("st.shared::cluster.f32 [%0], %1;" :: "r"(raddr), "f"(mysum)
                         : "memory");
        }
    }
    // Cluster barrier: arrive(release) orders the DSMEM stores; wait(acquire)
    // makes all 4 partials visible in local s_part.
    asm volatile("barrier.cluster.arrive.aligned;" ::: "memory");
    asm volatile("barrier.cluster.wait.aligned;"   ::: "memory");

    const float tot = (s_part[0] + s_part[1]) + (s_part[2] + s_part[3]);
    const float inv = (tot > 0.0f) ? (1.0f / tot) : 1.0f;   // 2^lcmax cancels

    // normalized store (coalesced float4)
    float* op = out + (size_t)b * 16384 + (size_t)u * 128 + v0;
#pragma unroll
    for (int j = 0; j < 32; j += 4) {
        float4 w = make_float4(acc[j] * inv, acc[j + 1] * inv,
                               acc[j + 2] * inv, acc[j + 3] * inv);
        *reinterpret_cast<float4*>(op + j) = w;
    }
}

extern "C" void kernel_launch(void* const* d_in, const int* in_sizes, int n_in,
                              void* d_out, int out_size)
{
    const float* mu    = (const float*)d_in[0];
    const float* sigma = (const float*)d_in[1];
    const float* cov12 = (const float*)d_in[2];
    const float* pi    = (const float*)d_in[3];
    float* out = (float*)d_out;
    gmm_hist_kernel<<<1024, 128>>>(mu, sigma, cov12, pi, out);
}

// round 8
// speedup vs baseline: 1.4015x; 1.0122x over previous
#include <cuda_runtime.h>
#include <cstdint>

// HistPredictor: splat B*K 2D Gaussians onto 128x128 grids, normalize per batch.
// B=256, K=16, grid 128x128 over [-2,2]^2, MIN_SIGMA=0.001.
//
// R8: 4-CTA cluster per batch + DSMEM norm (R4), packed-incremental f32x2
// exponent recurrence (R3, 2 slots/2pts), ex2.approx.f16x2 (R7, 1 MUFU/2pts),
// packed f32x2 accumulate (1 slot/2pts). Exponents rebased by -lcmax so they
// are <=0 (f16-safe; 2^lcmax cancels in the normalization).

#define KMIX 16

__device__ __forceinline__ unsigned long long pack2(float lo, float hi) {
    unsigned long long r;
    asm("mov.b64 %0, {%1, %2};" : "=l"(r) : "f"(lo), "f"(hi));
    return r;
}
__device__ __forceinline__ void unpack2(float& lo, float& hi, unsigned long long p) {
    asm("mov.b64 {%0, %1}, %2;" : "=f"(lo), "=f"(hi) : "l"(p));
}
__device__ __forceinline__ unsigned long long add2(unsigned long long a, unsigned long long b) {
    unsigned long long r;
    asm("add.rn.f32x2 %0, %1, %2;" : "=l"(r) : "l"(a), "l"(b));
    return r;
}

__global__ __launch_bounds__(128, 8) __cluster_dims__(4, 1, 1)
void gmm_hist_kernel(const float* __restrict__ mu,
                     const float* __restrict__ sigma,
                     const float* __restrict__ cov12,
                     const float* __restrict__ pi,
                     float* __restrict__ out)
{
    // log2-domain coefficients: e = a2*du^2 + b2*du*dv + c2*dv^2 + (lc - lcmax)
    __shared__ float s_a[KMIX], s_b[KMIX], s_c[KMIX], s_c2[KMIX];
    __shared__ float s_mu[KMIX], s_mv[KMIX], s_lc[KMIX];
    __shared__ float s_R[KMIX], s_S[KMIX], s_R8[KMIX];
    __shared__ float s_red[4];
    __shared__ float s_part[4];

    const int blk = blockIdx.x;
    const int b = blk >> 2;        // batch
    const int q = blk & 3;         // u-quarter == cluster ctarank
    const int t = threadIdx.x;

    const float H   = 4.0f / 127.0f;
    const float L2E = 1.4426950408889634f;

    if (t < KMIX) {
        const int idx = b * KMIX + t;
        float su = fmaxf(sigma[idx * 2 + 0], 0.001f);
        float sv = fmaxf(sigma[idx * 2 + 1], 0.001f);
        float su2 = su * su;
        float sv2 = sv * sv;
        float c11 = su2 + 1e-6f;
        float c22 = sv2 + 1e-6f;
        float off = cov12[idx];
        float det_full = c11 * c22 - off * off;
        // valid = (det_full > 0) & ~isnan(det_full); NaN>0 is false -> covered.
        float ia, ib, ic, det;
        if (det_full > 0.0f) {
            float rdet = 1.0f / det_full;
            ia = c22 * rdet;
            ib = -off * rdet;
            ic = c11 * rdet;
            det = det_full;
        } else {
            ia = 1.0f / su2;
            ib = 0.0f;
            ic = 1.0f / sv2;
            det = su2 * sv2;
        }
        float a2 = -0.5f * L2E * ia;
        float b2 = -L2E * ib;
        float c2 = -0.5f * L2E * ic;   // strictly < 0
        s_a[t]  = a2;
        s_b[t]  = b2;
        s_c[t]  = c2;
        s_c2[t] = 2.0f * c2;
        float R = c2 * (H * H);        // quadratic-in-j coefficient, < 0
        s_R[t]  = R;
        s_R8[t] = 8.0f * R;
        s_S[t]  = -0.5f / R;
        s_mu[t] = mu[idx * 2 + 0];
        s_mv[t] = mu[idx * 2 + 1];
        float coef = pi[idx] / (6.283185307179586f * sqrtf(det + 1e-6f));
        s_lc[t]   = __log2f(coef);     // -inf for coef==0
    }
    __syncthreads();

    // rebase: exponents shifted by -lcmax (<=0, f16-safe); cancels in normalize
    float lcmax = s_lc[0];
#pragma unroll
    for (int k = 1; k < KMIX; k++) lcmax = fmaxf(lcmax, s_lc[k]);

    // Thread t owns u = q*32 + (t>>2), v in [(t&3)*32, +32)
    const int u  = q * 32 + (t >> 2);
    const int v0 = (t & 3) * 32;
    const float uc    = -2.0f + (float)u  * H;
    const float vbase = -2.0f + (float)v0 * H;

    unsigned long long acc[16];   // packed f32 pairs (j even, j odd)
#pragma unroll
    for (int i = 0; i < 16; i++) acc[i] = 0ull;

#pragma unroll 1
    for (int k = 0; k < KMIX; k++) {
        const float du  = uc    - s_mu[k];
        const float dv0 = vbase - s_mv[k];
        // e(j) = P' + Q*j + R*j^2,  dv = dv0 + j*H,  P' includes lc - lcmax
        const float R = s_R[k];
        const float Q = fmaf(s_c2[k], dv0, s_b[k] * du) * H;
        const float P = fmaf(fmaf(s_b[k], dv0, s_a[k] * du), du,
                             fmaf(s_c[k] * dv0, dv0, s_lc[k] - lcmax));

        // warp-uniform skip: max of concave e' over j in [0,31] vs -20
        float jc = fminf(fmaxf(Q * s_S[k], 0.0f), 31.0f);
        float ev = fmaf(jc, fmaf(R, jc, Q), P);
        if (__ballot_sync(0xffffffffu, ev >= -20.0f) == 0u) continue;

        // packed incremental recurrence over pairs (j=2i, 2i+1):
        //   ep_{i+1} = ep_i + dp_i ;  dp_{i+1} = dp_i + (8R, 8R)
        unsigned long long ep = pack2(P, P + Q + R);
        unsigned long long dp = pack2(2.0f * Q + 4.0f * R, 2.0f * Q + 8.0f * R);
        const unsigned long long stp = pack2(s_R8[k], s_R8[k]);

#pragma unroll
        for (int i = 0; i < 16; i++) {
            float elo, ehi;
            unpack2(elo, ehi, ep);
            uint32_t g2;
            asm("{\n\t"
                ".reg .b32 h2;\n\t"
                "cvt.rn.f16x2.f32 h2, %1, %2;\n\t"    // hi = ehi, lo = elo
                "ex2.approx.f16x2 %0, h2;\n\t"
                "}"
                : "=r"(g2) : "f"(ehi), "f"(elo));
            float g0, g1;
            asm("{\n\t"
                ".reg .b16 lo, hi;\n\t"
                "mov.b32 {lo, hi}, %2;\n\t"
                "cvt.f32.f16 %0, lo;\n\t"
                "cvt.f32.f16 %1, hi;\n\t"
                "}"
                : "=f"(g0), "=f"(g1) : "r"(g2));
            acc[i] = add2(acc[i], pack2(g0, g1));     // packed accumulate
            ep = add2(ep, dp);
            dp = add2(dp, stp);
        }
    }

    // CTA partial sum (this u-quarter, rebased domain)
    float s = 0.0f;
#pragma unroll
    for (int i = 0; i < 16; i++) {
        float lo, hi;
        unpack2(lo, hi, acc[i]);
        s += lo + hi;
    }
#pragma unroll
    for (int o = 16; o > 0; o >>= 1) s += __shfl_xor_sync(0xffffffffu, s, o);
    const int warp = t >> 5;
    const int lane = t & 31;
    if (lane == 0) s_red[warp] = s;
    __syncthreads();

    // Thread 0 scatters this CTA's partial into slot q of all 4 cluster CTAs.
    if (t == 0) {
        float mysum = s_red[0] + s_red[1] + s_red[2] + s_red[3];
        uint32_t laddr;
        asm("{ .reg .u64 tmp; cvta.to.shared.u64 tmp, %1; cvt.u32.u64 %0, tmp; }"
            : "=r"(laddr) : "l"(&s_part[q]));
#pragma unroll
        for (int r = 0; r < 4; r++) {
            uint32_t raddr;
            asm("mapa.shared::cluster.u32 %0, %1, %2;" : "=r"(raddr) : "r"(laddr), "r"(r));
            asm volatile("st.shared::cluster.f32 [%0], %1;" :: "r"(raddr), "f"(mysum)
                         : "memory");
        }
    }
    // Cluster barrier: arrive(release) orders the DSMEM stores; wait(acquire)
    // makes all 4 partials visible in local s_part.
    asm volatile("barrier.cluster.arrive.aligned;" ::: "memory");
    asm volatile("barrier.cluster.wait.aligned;"   ::: "memory");

    const float tot = (s_part[0] + s_part[1]) + (s_part[2] + s_part[3]);
    const float inv = (tot > 0.0f) ? (1.0f / tot) : 1.0f;   // 2^lcmax cancels

    // normalized store (coalesced float4)
    float* op = out + (size_t)b * 16384 + (size_t)u * 128 + v0;
#pragma unroll
    for (int i = 0; i < 16; i += 2) {
        float x0, x1, x2, x3;
        unpack2(x0, x1, acc[i]);
        unpack2(x2, x3, acc[i + 1]);
        *reinterpret_cast<float4*>(op + i * 2) =
            make_float4(x0 * inv, x1 * inv, x2 * inv, x3 * inv);
    }
}

extern "C" void kernel_launch(void* const* d_in, const int* in_sizes, int n_in,
                              void* d_out, int out_size)
{
    const float* mu    = (const float*)d_in[0];
    const float* sigma = (const float*)d_in[1];
    const float* cov12 = (const float*)d_in[2];
    const float* pi    = (const float*)d_in[3];
    float* out = (float*)d_out;
    gmm_hist_kernel<<<1024, 128>>>(mu, sigma, cov12, pi, out);
}